// round 1
// baseline (speedup 1.0000x reference)
#include <cuda_runtime.h>

#define Bn 32
#define Tn 65536
#define TP1 65537
#define NCHUNK 16
#define BTH 256
#define SPT 16   /* Tn / (NCHUNK*BTH) */

// ---------------- scratch (device globals; no allocation) ----------------
static __device__ int    g_segids[Bn * Tn];         // 8 MB
static __device__ float4 g_segsum[Bn * TP1];        // 33.6 MB (param sums per segment)
static __device__ float  g_segcnt[Bn * TP1];        // 8.4 MB
static __device__ float4 g_mc[Bn * Tn];             // 32 MB (m00, m10, c1, c2)
static __device__ float  g_bx[Bn * Tn];             // 8 MB  (b0 * xc)
static __device__ float4 g_chunkM[Bn * NCHUNK];     // chunk transforms
static __device__ float2 g_chunkC[Bn * NCHUNK];
static __device__ float2 g_chunkIn[Bn * NCHUNK];    // incoming state per chunk

// ---------------- constants ----------------
#define MIN_W_F     0.007853981633974483f   /* 2*pi*20/16000 */
#define LOG2_400_F  8.643856189774724f      /* log2(pi/MIN_W) = log2(400) */
#define LOG2_20_F   4.321928094887363f      /* log2(2.0/0.1) */

__device__ __forceinline__ float fast_sigmoid(float v) {
    return __fdividef(1.0f, 1.0f + __expf(-v));
}

// =====================================================================
// K1: per-row inclusive cumsum of onsets -> seg ids; per-segment param
//     sums/counts via flush-on-change atomics.
// =====================================================================
__global__ void __launch_bounds__(1024) k_seg(const int* __restrict__ onsets,
                                              const float4* __restrict__ params4) {
    const int CH = Tn / 1024;   // 64
    int row = blockIdx.x;
    int tid = threadIdx.x;
    long base = (long)row * Tn + (long)tid * CH;

    // pass A: count onsets in this thread's chunk (vectorized)
    const int4* o4 = reinterpret_cast<const int4*>(onsets + base);
    int total = 0;
#pragma unroll
    for (int i = 0; i < CH / 4; i++) {
        int4 v = o4[i];
        total += v.x + v.y + v.z + v.w;
    }

    // block scan of per-thread totals (warp shfl + warp sums)
    __shared__ int wsum[32];
    int lane = tid & 31, wid = tid >> 5;
    int incl = total;
#pragma unroll
    for (int o = 1; o < 32; o <<= 1) {
        int n = __shfl_up_sync(0xffffffffu, incl, o);
        if (lane >= o) incl += n;
    }
    if (lane == 31) wsum[wid] = incl;
    __syncthreads();
    if (wid == 0) {
        int v = wsum[lane];
        int wincl = v;
#pragma unroll
        for (int o = 1; o < 32; o <<= 1) {
            int n = __shfl_up_sync(0xffffffffu, wincl, o);
            if (lane >= o) wincl += n;
        }
        wsum[lane] = wincl - v;   // exclusive
    }
    __syncthreads();
    int id = (incl - total) + wsum[wid];   // onsets strictly before chunk

    // pass B: ids + segment accumulation (flush only on segment change)
    float4 acc = make_float4(0.f, 0.f, 0.f, 0.f);
    float accn = 0.f;
    int cur = -1;
    for (int i = 0; i < CH; i++) {
        long idx = base + i;
        id += onsets[idx];
        g_segids[idx] = id;
        if (id != cur) {
            if (cur >= 0) {
                int si = row * TP1 + cur;
                atomicAdd(&g_segsum[si].x, acc.x);
                atomicAdd(&g_segsum[si].y, acc.y);
                atomicAdd(&g_segsum[si].z, acc.z);
                atomicAdd(&g_segsum[si].w, acc.w);
                atomicAdd(&g_segcnt[si], accn);
            }
            acc = make_float4(0.f, 0.f, 0.f, 0.f);
            accn = 0.f;
            cur = id;
        }
        float4 p = params4[idx];
        acc.x += p.x; acc.y += p.y; acc.z += p.z; acc.w += p.w;
        accn += 1.f;
    }
    if (cur >= 0) {
        int si = row * TP1 + cur;
        atomicAdd(&g_segsum[si].x, acc.x);
        atomicAdd(&g_segsum[si].y, acc.y);
        atomicAdd(&g_segsum[si].z, acc.z);
        atomicAdd(&g_segsum[si].w, acc.w);
        atomicAdd(&g_segcnt[si], accn);
    }
}

// =====================================================================
// K2: elementwise — segment avg -> sigmoids -> distance/mu/w/q ->
//     pluck comb -> biquad coefficients -> affine step (m, c, bx)
// =====================================================================
__device__ __forceinline__ float seg_dist(int row, int j) {
    int s = g_segids[row * Tn + j];
    int si = row * TP1 + s;
    float inv = __fdividef(1.f, fmaxf(g_segcnt[si], 1.f));
    float p0 = g_segsum[si].x * inv;
    float sg = fast_sigmoid(p0);
    return 0.1f * exp2f(sg * LOG2_20_F);
}

__global__ void __launch_bounds__(256) k_coef(const float* __restrict__ f0,
                                              const float* __restrict__ x) {
    int idx = blockIdx.x * 256 + threadIdx.x;
    int row = idx >> 16;
    int t = idx & (Tn - 1);

    int si = row * TP1 + g_segids[idx];
    float4 s4 = g_segsum[si];
    float invc = __fdividef(1.f, fmaxf(g_segcnt[si], 1.f));
    float a0p = s4.x * invc, a1p = s4.y * invc, a2p = s4.z * invc, a3p = s4.w * invc;

    float dist  = 0.1f * exp2f(fast_sigmoid(a0p) * LOG2_20_F);
    float wmod  = fast_sigmoid(a1p);
    float qmod  = fast_sigmoid(a2p);
    float mu    = fast_sigmoid(a3p);

    // pluck comb
    float p = f0[idx] * mu;
    float z = floorf(p);
    float alfa = p - z;
    int zi = (int)z;
    int j1 = t - (zi + 1);
    int j2 = t - (zi + 2);
    float xd = x[idx] * dist;
    float x1 = (j1 >= 0) ? x[row * Tn + j1] * seg_dist(row, j1) : 0.f;
    float x2 = (j2 >= 0) ? x[row * Tn + j2] * seg_dist(row, j2) : 0.f;
    float xc = xd - (1.f - alfa) * x1 - alfa * x2;

    // RBJ low-pass coefficients (half-angle: avoids 1-cos cancellation)
    float w = MIN_W_F * exp2f(wmod * LOG2_400_F);
    float q = 0.1f * exp2f(qmod * LOG2_20_F);
    float sh, ch;
    __sincosf(0.5f * w, &sh, &ch);
    float one_m_cw = 2.f * sh * sh;
    float cw = 1.f - one_m_cw;
    float sw = 2.f * sh * ch;
    float alpha = __fdividef(sw, 2.f * q);
    float inva0 = __fdividef(1.f, 1.f + alpha);
    float b0 = 0.5f * one_m_cw * inva0;
    float b1 = one_m_cw * inva0;
    float b2 = b0;
    float a1 = -2.f * cw * inva0;
    float a2 = (1.f - alpha) * inva0;

    // affine state step: s1' = m00*s1 + s2 + c1;  s2' = m10*s1 + c2; y = bx + s1
    float m00 = -a1;
    float m10 = -a2;
    float v1 = b1 - a1 * b0;
    float v2 = b2 - a2 * b0;
    g_mc[idx] = make_float4(m00, m10, v1 * xc, v2 * xc);
    g_bx[idx] = b0 * xc;
}

// =====================================================================
// Affine compose helper: later L after earlier E (2x2 M + 2-vec c)
// =====================================================================
#define COMPOSE(E00,E01,E10,E11,Ec1,Ec2, L00,L01,L10,L11,Lc1,Lc2, \
                N00,N01,N10,N11,Nc1,Nc2)                          \
    do {                                                          \
        N00 = fmaf(L00, E00, L01 * E10);                          \
        N01 = fmaf(L00, E01, L01 * E11);                          \
        N10 = fmaf(L10, E00, L11 * E10);                          \
        N11 = fmaf(L10, E01, L11 * E11);                          \
        Nc1 = fmaf(L00, Ec1, fmaf(L01, Ec2, Lc1));                \
        Nc2 = fmaf(L10, Ec1, fmaf(L11, Ec2, Lc2));                \
    } while (0)

// per-thread sequential compose of SPT steps (step matrices are [[m00,1],[m10,0]])
__device__ __forceinline__ void thread_compose(long base,
        float& A00, float& A01, float& A10, float& A11, float& c1, float& c2) {
    A00 = 1.f; A01 = 0.f; A10 = 0.f; A11 = 1.f; c1 = 0.f; c2 = 0.f;
#pragma unroll
    for (int i = 0; i < SPT; i++) {
        float4 m = g_mc[base + i];
        float n00 = fmaf(m.x, A00, A10);
        float n01 = fmaf(m.x, A01, A11);
        float n10 = m.y * A00;
        float n11 = m.y * A01;
        float t1  = fmaf(m.x, c1, c2) + m.z;
        float t2  = fmaf(m.y, c1, m.w);
        A00 = n00; A01 = n01; A10 = n10; A11 = n11; c1 = t1; c2 = t2;
    }
}

// K3a: per-block chunk transform (ordered tree reduce)
__global__ void __launch_bounds__(BTH) k_scanA() {
    int tid = threadIdx.x;
    long base = (long)blockIdx.x * (BTH * SPT) + (long)tid * SPT;
    float A00, A01, A10, A11, c1, c2;
    thread_compose(base, A00, A01, A10, A11, c1, c2);

    __shared__ float s00[BTH], s01[BTH], s10[BTH], s11[BTH], sc1[BTH], sc2[BTH];
    s00[tid] = A00; s01[tid] = A01; s10[tid] = A10; s11[tid] = A11;
    sc1[tid] = c1;  sc2[tid] = c2;
    for (int st = 1; st < BTH; st <<= 1) {
        __syncthreads();
        if ((tid & (2 * st - 1)) == 0) {
            int j = tid + st;
            float L00 = s00[j], L01 = s01[j], L10 = s10[j], L11 = s11[j];
            float Lc1 = sc1[j], Lc2 = sc2[j];
            float E00 = s00[tid], E01 = s01[tid], E10 = s10[tid], E11 = s11[tid];
            float Ec1 = sc1[tid], Ec2 = sc2[tid];
            float N00, N01, N10, N11, Nc1, Nc2;
            COMPOSE(E00,E01,E10,E11,Ec1,Ec2, L00,L01,L10,L11,Lc1,Lc2,
                    N00,N01,N10,N11,Nc1,Nc2);
            s00[tid] = N00; s01[tid] = N01; s10[tid] = N10; s11[tid] = N11;
            sc1[tid] = Nc1; sc2[tid] = Nc2;
        }
    }
    __syncthreads();
    if (tid == 0) {
        g_chunkM[blockIdx.x] = make_float4(s00[0], s01[0], s10[0], s11[0]);
        g_chunkC[blockIdx.x] = make_float2(sc1[0], sc2[0]);
    }
}

// K3b: tiny per-row sequential scan over NCHUNK chunk transforms
__global__ void k_scanB() {
    int r = threadIdx.x;
    if (r >= Bn) return;
    float s1 = 0.f, s2 = 0.f;
    for (int k = 0; k < NCHUNK; k++) {
        int i = r * NCHUNK + k;
        g_chunkIn[i] = make_float2(s1, s2);
        float4 M = g_chunkM[i];
        float2 c = g_chunkC[i];
        float n1 = fmaf(M.x, s1, fmaf(M.y, s2, c.x));
        float n2 = fmaf(M.z, s1, fmaf(M.w, s2, c.y));
        s1 = n1; s2 = n2;
    }
}

// K3c: block Kogge-Stone scan -> per-thread incoming state -> replay
__global__ void __launch_bounds__(BTH) k_replay(float* __restrict__ out) {
    int tid = threadIdx.x;
    long base = (long)blockIdx.x * (BTH * SPT) + (long)tid * SPT;
    float r00, r01, r10, r11, rc1, rc2;
    thread_compose(base, r00, r01, r10, r11, rc1, rc2);

    __shared__ float s00[BTH], s01[BTH], s10[BTH], s11[BTH], sc1[BTH], sc2[BTH];
    s00[tid] = r00; s01[tid] = r01; s10[tid] = r10; s11[tid] = r11;
    sc1[tid] = rc1; sc2[tid] = rc2;
    __syncthreads();
    for (int st = 1; st < BTH; st <<= 1) {
        float E00 = 0.f, E01 = 0.f, E10 = 0.f, E11 = 0.f, Ec1 = 0.f, Ec2 = 0.f;
        bool has = (tid >= st);
        if (has) {
            E00 = s00[tid - st]; E01 = s01[tid - st];
            E10 = s10[tid - st]; E11 = s11[tid - st];
            Ec1 = sc1[tid - st]; Ec2 = sc2[tid - st];
        }
        __syncthreads();
        if (has) {
            float N00, N01, N10, N11, Nc1, Nc2;
            COMPOSE(E00,E01,E10,E11,Ec1,Ec2, r00,r01,r10,r11,rc1,rc2,
                    N00,N01,N10,N11,Nc1,Nc2);
            r00 = N00; r01 = N01; r10 = N10; r11 = N11; rc1 = Nc1; rc2 = Nc2;
            s00[tid] = r00; s01[tid] = r01; s10[tid] = r10; s11[tid] = r11;
            sc1[tid] = rc1; sc2[tid] = rc2;
        }
        __syncthreads();
    }
    // exclusive prefix for this thread (inclusive of tid-1)
    float P00 = 1.f, P01 = 0.f, P10 = 0.f, P11 = 1.f, pc1 = 0.f, pc2 = 0.f;
    if (tid > 0) {
        P00 = s00[tid - 1]; P01 = s01[tid - 1];
        P10 = s10[tid - 1]; P11 = s11[tid - 1];
        pc1 = sc1[tid - 1]; pc2 = sc2[tid - 1];
    }
    float2 cin = g_chunkIn[blockIdx.x];
    float st1 = fmaf(P00, cin.x, fmaf(P01, cin.y, pc1));
    float st2 = fmaf(P10, cin.x, fmaf(P11, cin.y, pc2));

    // replay
#pragma unroll
    for (int i = 0; i < SPT; i++) {
        float4 m = g_mc[base + i];
        float bx = g_bx[base + i];
        out[base + i] = bx + st1;
        float n1 = fmaf(m.x, st1, st2) + m.z;
        float n2 = fmaf(m.y, st1, m.w);
        st1 = n1; st2 = n2;
    }
}

// =====================================================================
extern "C" void kernel_launch(void* const* d_in, const int* in_sizes, int n_in,
                              void* d_out, int out_size) {
    const float* f0     = (const float*)d_in[0];
    const float* x      = (const float*)d_in[1];
    const float* params = (const float*)d_in[2];
    const int*   onsets = (const int*)d_in[3];
    float* out = (float*)d_out;

    void *pSum = nullptr, *pCnt = nullptr;
    cudaGetSymbolAddress(&pSum, g_segsum);
    cudaGetSymbolAddress(&pCnt, g_segcnt);
    cudaMemsetAsync(pSum, 0, sizeof(float4) * (size_t)Bn * TP1);
    cudaMemsetAsync(pCnt, 0, sizeof(float) * (size_t)Bn * TP1);

    k_seg<<<Bn, 1024>>>(onsets, (const float4*)params);
    k_coef<<<(Bn * Tn) / 256, 256>>>(f0, x);
    k_scanA<<<Bn * NCHUNK, BTH>>>();
    k_scanB<<<1, Bn>>>();
    k_replay<<<Bn * NCHUNK, BTH>>>(out);
}

// round 2
// speedup vs baseline: 2.6176x; 2.6176x over previous
#include <cuda_runtime.h>

#define Bn 32
#define Tn 65536
#define TILE 2048
#define NT 32              /* tiles per row = Tn/TILE */
#define ROUNDS 8           /* TILE/256 */
#define NCHUNK 32
#define BTH 256
#define SPT 8              /* Tn/(NCHUNK*BTH) */
#define SEGCAP (Tn + 2)

// ---------------- scratch (device globals) ----------------
static __device__ int    g_tileOn[Bn * NT];
static __device__ float4 g_tileP[Bn * NT];
static __device__ int    g_segids[Bn * Tn];       // 8 MB
static __device__ int    g_S[Bn * SEGCAP];        // 8.4 MB  segment start index
static __device__ float4 g_Bnd[Bn * SEGCAP];      // 33.6 MB exclusive param prefix at start
static __device__ float4 g_mc[Bn * Tn];           // 32 MB
static __device__ float  g_bx[Bn * Tn];           // 8 MB
static __device__ float4 g_chunkM[Bn * NCHUNK];
static __device__ float2 g_chunkC[Bn * NCHUNK];
static __device__ float2 g_chunkIn[Bn * NCHUNK];

#define MIN_W_F     0.007853981633974483f
#define LOG2_400_F  8.643856189774724f
#define LOG2_20_F   4.321928094887363f

__device__ __forceinline__ float fast_sigmoid(float v) {
    return __fdividef(1.0f, 1.0f + __expf(-v));
}

// =====================================================================
// K1a: per-tile totals of onsets (int) + params (float4), coalesced.
// =====================================================================
__global__ void __launch_bounds__(256) k_tile(const int* __restrict__ onsets,
                                              const float4* __restrict__ params) {
    int blk = blockIdx.x;
    int row = blk / NT, tile = blk % NT;
    long base = (long)row * Tn + (long)tile * TILE;
    int tid = threadIdx.x;

    int o = 0;
    float4 ps = make_float4(0.f, 0.f, 0.f, 0.f);
#pragma unroll
    for (int r = 0; r < ROUNDS; r++) {
        long idx = base + r * 256 + tid;
        o += onsets[idx];
        float4 p = params[idx];
        ps.x += p.x; ps.y += p.y; ps.z += p.z; ps.w += p.w;
    }
#pragma unroll
    for (int off = 16; off; off >>= 1) {
        o    += __shfl_down_sync(0xffffffffu, o, off);
        ps.x += __shfl_down_sync(0xffffffffu, ps.x, off);
        ps.y += __shfl_down_sync(0xffffffffu, ps.y, off);
        ps.z += __shfl_down_sync(0xffffffffu, ps.z, off);
        ps.w += __shfl_down_sync(0xffffffffu, ps.w, off);
    }
    __shared__ int    so[8];
    __shared__ float4 sp[8];
    int lane = tid & 31, wid = tid >> 5;
    if (lane == 0) { so[wid] = o; sp[wid] = ps; }
    __syncthreads();
    if (tid == 0) {
        int ot = 0; float4 pt = make_float4(0.f, 0.f, 0.f, 0.f);
#pragma unroll
        for (int w = 0; w < 8; w++) {
            ot += so[w];
            pt.x += sp[w].x; pt.y += sp[w].y; pt.z += sp[w].z; pt.w += sp[w].w;
        }
        g_tileOn[blk] = ot;
        g_tileP[blk] = pt;
    }
}

// =====================================================================
// K1b: warp-per-row scan of tile totals -> exclusive tile offsets;
//      write row sentinels (segment 0 start and end-sentinel).
// =====================================================================
__global__ void __launch_bounds__(1024) k_tileScan() {
    int row = threadIdx.x >> 5, lane = threadIdx.x & 31;
    int i = row * NT + lane;
    int o = g_tileOn[i];
    float4 p = g_tileP[i];
    int oi = o;
    float4 pi = p;
#pragma unroll
    for (int off = 1; off < 32; off <<= 1) {
        int   to = __shfl_up_sync(0xffffffffu, oi, off);
        float a  = __shfl_up_sync(0xffffffffu, pi.x, off);
        float b  = __shfl_up_sync(0xffffffffu, pi.y, off);
        float c  = __shfl_up_sync(0xffffffffu, pi.z, off);
        float d  = __shfl_up_sync(0xffffffffu, pi.w, off);
        if (lane >= off) { oi += to; pi.x += a; pi.y += b; pi.z += c; pi.w += d; }
    }
    g_tileOn[i] = oi - o;   // exclusive
    g_tileP[i]  = make_float4(pi.x - p.x, pi.y - p.y, pi.z - p.z, pi.w - p.w);
    if (lane == 31) {
        int nOn = oi;       // total onsets in row = last segment id
        g_S[row * SEGCAP + nOn + 1]   = Tn;
        g_Bnd[row * SEGCAP + nOn + 1] = pi;
    }
    if (lane == 0) {
        g_S[row * SEGCAP]   = 0;
        g_Bnd[row * SEGCAP] = make_float4(0.f, 0.f, 0.f, 0.f);
    }
}

// =====================================================================
// K1c: full in-tile scan -> segids (coalesced) + boundary scatter at onsets.
// =====================================================================
__global__ void __launch_bounds__(256) k_ids(const int* __restrict__ onsets,
                                             const float4* __restrict__ params) {
    int blk = blockIdx.x;
    int row = blk / NT, tile = blk % NT;
    long rowbase = (long)row * Tn;
    long base = rowbase + (long)tile * TILE;
    int tid = threadIdx.x, lane = tid & 31, wid = tid >> 5;
    int rowoff = row * SEGCAP;

    __shared__ int    so[8];
    __shared__ float4 sp[8];

    int    carO = g_tileOn[blk];
    float4 carP = g_tileP[blk];

#pragma unroll
    for (int r = 0; r < ROUNDS; r++) {
        long idx = base + r * 256 + tid;
        int o = onsets[idx];
        float4 p = params[idx];
        int oi = o;
        float4 pi = p;
#pragma unroll
        for (int off = 1; off < 32; off <<= 1) {
            int   to = __shfl_up_sync(0xffffffffu, oi, off);
            float a  = __shfl_up_sync(0xffffffffu, pi.x, off);
            float b  = __shfl_up_sync(0xffffffffu, pi.y, off);
            float c  = __shfl_up_sync(0xffffffffu, pi.z, off);
            float d  = __shfl_up_sync(0xffffffffu, pi.w, off);
            if (lane >= off) { oi += to; pi.x += a; pi.y += b; pi.z += c; pi.w += d; }
        }
        if (lane == 31) { so[wid] = oi; sp[wid] = pi; }
        __syncthreads();
        int wpo = 0, bto = 0;
        float4 wpp = make_float4(0.f, 0.f, 0.f, 0.f);
        float4 btp = make_float4(0.f, 0.f, 0.f, 0.f);
#pragma unroll
        for (int w = 0; w < 8; w++) {
            if (w == wid) { wpo = bto; wpp = btp; }
            bto += so[w];
            btp.x += sp[w].x; btp.y += sp[w].y; btp.z += sp[w].z; btp.w += sp[w].w;
        }
        int id = carO + wpo + oi;
        g_segids[idx] = id;
        if (o) {
            g_S[rowoff + id] = (int)(idx - rowbase);
            g_Bnd[rowoff + id] = make_float4(carP.x + wpp.x + pi.x - p.x,
                                             carP.y + wpp.y + pi.y - p.y,
                                             carP.z + wpp.z + pi.z - p.z,
                                             carP.w + wpp.w + pi.w - p.w);
        }
        carO += bto;
        carP.x += btp.x; carP.y += btp.y; carP.z += btp.z; carP.w += btp.w;
        __syncthreads();
    }
}

// =====================================================================
// K2: elementwise — segment avg via boundary diff -> comb -> biquad coefs
// =====================================================================
__device__ __forceinline__ float seg_dist(int row, int j) {
    int s = g_segids[row * Tn + j];
    int ro = row * SEGCAP + s;
    float num = g_Bnd[ro + 1].x - g_Bnd[ro].x;
    float den = (float)(g_S[ro + 1] - g_S[ro]);
    float p0 = num * __fdividef(1.f, fmaxf(den, 1.f));
    return 0.1f * exp2f(fast_sigmoid(p0) * LOG2_20_F);
}

__global__ void __launch_bounds__(256) k_coef(const float* __restrict__ f0,
                                              const float* __restrict__ x) {
    int idx = blockIdx.x * 256 + threadIdx.x;
    int row = idx >> 16;
    int t = idx & (Tn - 1);

    int ro = row * SEGCAP + g_segids[idx];
    int s0 = g_S[ro], s1 = g_S[ro + 1];
    float4 B0 = g_Bnd[ro], B1 = g_Bnd[ro + 1];
    float invc = __fdividef(1.f, fmaxf((float)(s1 - s0), 1.f));
    float a0p = (B1.x - B0.x) * invc;
    float a1p = (B1.y - B0.y) * invc;
    float a2p = (B1.z - B0.z) * invc;
    float a3p = (B1.w - B0.w) * invc;

    float dist = 0.1f * exp2f(fast_sigmoid(a0p) * LOG2_20_F);
    float wmod = fast_sigmoid(a1p);
    float qmod = fast_sigmoid(a2p);
    float mu   = fast_sigmoid(a3p);

    // pluck comb
    float p = f0[idx] * mu;
    float z = floorf(p);
    float alfa = p - z;
    int zi = (int)z;
    int j1 = t - (zi + 1);
    int j2 = t - (zi + 2);
    float xd = x[idx] * dist;
    float x1 = (j1 >= 0) ? x[row * Tn + j1] * seg_dist(row, j1) : 0.f;
    float x2 = (j2 >= 0) ? x[row * Tn + j2] * seg_dist(row, j2) : 0.f;
    float xc = xd - (1.f - alfa) * x1 - alfa * x2;

    // RBJ LP coefficients (half-angle to avoid 1-cos cancellation)
    float w = MIN_W_F * exp2f(wmod * LOG2_400_F);
    float q = 0.1f * exp2f(qmod * LOG2_20_F);
    float sh, ch;
    __sincosf(0.5f * w, &sh, &ch);
    float one_m_cw = 2.f * sh * sh;
    float cw = 1.f - one_m_cw;
    float sw = 2.f * sh * ch;
    float alpha = __fdividef(sw, 2.f * q);
    float inva0 = __fdividef(1.f, 1.f + alpha);
    float b0 = 0.5f * one_m_cw * inva0;
    float b1 = one_m_cw * inva0;
    float b2 = b0;
    float a1 = -2.f * cw * inva0;
    float a2 = (1.f - alpha) * inva0;

    float m00 = -a1;
    float m10 = -a2;
    float v1 = b1 - a1 * b0;
    float v2 = b2 - a2 * b0;
    g_mc[idx] = make_float4(m00, m10, v1 * xc, v2 * xc);
    g_bx[idx] = b0 * xc;
}

// =====================================================================
// Affine compose: later L after earlier E
// =====================================================================
#define COMPOSE(E00,E01,E10,E11,Ec1,Ec2, L00,L01,L10,L11,Lc1,Lc2, \
                N00,N01,N10,N11,Nc1,Nc2)                          \
    do {                                                          \
        N00 = fmaf(L00, E00, L01 * E10);                          \
        N01 = fmaf(L00, E01, L01 * E11);                          \
        N10 = fmaf(L10, E00, L11 * E10);                          \
        N11 = fmaf(L10, E01, L11 * E11);                          \
        Nc1 = fmaf(L00, Ec1, fmaf(L01, Ec2, Lc1));                \
        Nc2 = fmaf(L10, Ec1, fmaf(L11, Ec2, Lc2));                \
    } while (0)

__device__ __forceinline__ void load_mc(long base, float4 m[SPT]) {
#pragma unroll
    for (int i = 0; i < SPT; i++) m[i] = g_mc[base + i];
}

__device__ __forceinline__ void compose_regs(const float4 m[SPT],
        float& A00, float& A01, float& A10, float& A11, float& c1, float& c2) {
    A00 = 1.f; A01 = 0.f; A10 = 0.f; A11 = 1.f; c1 = 0.f; c2 = 0.f;
#pragma unroll
    for (int i = 0; i < SPT; i++) {
        float n00 = fmaf(m[i].x, A00, A10);
        float n01 = fmaf(m[i].x, A01, A11);
        float n10 = m[i].y * A00;
        float n11 = m[i].y * A01;
        float t1  = fmaf(m[i].x, c1, c2) + m[i].z;
        float t2  = fmaf(m[i].y, c1, m[i].w);
        A00 = n00; A01 = n01; A10 = n10; A11 = n11; c1 = t1; c2 = t2;
    }
}

// K3a: per-chunk total transform (ordered tree reduce)
__global__ void __launch_bounds__(BTH) k_scanA() {
    int tid = threadIdx.x;
    long base = (long)blockIdx.x * (BTH * SPT) + (long)tid * SPT;
    float4 m[SPT];
    load_mc(base, m);
    float A00, A01, A10, A11, c1, c2;
    compose_regs(m, A00, A01, A10, A11, c1, c2);

    __shared__ float s00[BTH], s01[BTH], s10[BTH], s11[BTH], sc1[BTH], sc2[BTH];
    s00[tid] = A00; s01[tid] = A01; s10[tid] = A10; s11[tid] = A11;
    sc1[tid] = c1;  sc2[tid] = c2;
    for (int st = 1; st < BTH; st <<= 1) {
        __syncthreads();
        if ((tid & (2 * st - 1)) == 0) {
            int j = tid + st;
            float N00, N01, N10, N11, Nc1, Nc2;
            COMPOSE(s00[tid],s01[tid],s10[tid],s11[tid],sc1[tid],sc2[tid],
                    s00[j],  s01[j],  s10[j],  s11[j],  sc1[j],  sc2[j],
                    N00,N01,N10,N11,Nc1,Nc2);
            s00[tid] = N00; s01[tid] = N01; s10[tid] = N10; s11[tid] = N11;
            sc1[tid] = Nc1; sc2[tid] = Nc2;
        }
    }
    __syncthreads();
    if (tid == 0) {
        g_chunkM[blockIdx.x] = make_float4(s00[0], s01[0], s10[0], s11[0]);
        g_chunkC[blockIdx.x] = make_float2(sc1[0], sc2[0]);
    }
}

// K3b: warp-per-row Kogge-Stone over NCHUNK chunk transforms (all in regs)
__global__ void __launch_bounds__(1024) k_scanB() {
    int row = threadIdx.x >> 5, l = threadIdx.x & 31;
    int i = row * NCHUNK + l;
    float4 M = g_chunkM[i];
    float2 c = g_chunkC[i];
    float A00 = M.x, A01 = M.y, A10 = M.z, A11 = M.w, c1 = c.x, c2 = c.y;
#pragma unroll
    for (int off = 1; off < 32; off <<= 1) {
        float E00 = __shfl_up_sync(0xffffffffu, A00, off);
        float E01 = __shfl_up_sync(0xffffffffu, A01, off);
        float E10 = __shfl_up_sync(0xffffffffu, A10, off);
        float E11 = __shfl_up_sync(0xffffffffu, A11, off);
        float Ec1 = __shfl_up_sync(0xffffffffu, c1, off);
        float Ec2 = __shfl_up_sync(0xffffffffu, c2, off);
        if (l >= off) {
            float N00, N01, N10, N11, Nc1, Nc2;
            COMPOSE(E00,E01,E10,E11,Ec1,Ec2, A00,A01,A10,A11,c1,c2,
                    N00,N01,N10,N11,Nc1,Nc2);
            A00 = N00; A01 = N01; A10 = N10; A11 = N11; c1 = Nc1; c2 = Nc2;
        }
    }
    // incoming state for chunk l = c-part of inclusive scan at lane l-1
    float p1 = __shfl_up_sync(0xffffffffu, c1, 1);
    float p2 = __shfl_up_sync(0xffffffffu, c2, 1);
    if (l == 0) { p1 = 0.f; p2 = 0.f; }
    g_chunkIn[i] = make_float2(p1, p2);
}

// K3c: block KS scan -> per-thread incoming state -> replay
__global__ void __launch_bounds__(BTH) k_replay(float* __restrict__ out) {
    int tid = threadIdx.x;
    long base = (long)blockIdx.x * (BTH * SPT) + (long)tid * SPT;
    float4 m[SPT];
    load_mc(base, m);
    float r00, r01, r10, r11, rc1, rc2;
    compose_regs(m, r00, r01, r10, r11, rc1, rc2);

    __shared__ float s00[BTH], s01[BTH], s10[BTH], s11[BTH], sc1[BTH], sc2[BTH];
    s00[tid] = r00; s01[tid] = r01; s10[tid] = r10; s11[tid] = r11;
    sc1[tid] = rc1; sc2[tid] = rc2;
    __syncthreads();
    for (int st = 1; st < BTH; st <<= 1) {
        float E00 = 0.f, E01 = 0.f, E10 = 0.f, E11 = 0.f, Ec1 = 0.f, Ec2 = 0.f;
        bool has = (tid >= st);
        if (has) {
            E00 = s00[tid - st]; E01 = s01[tid - st];
            E10 = s10[tid - st]; E11 = s11[tid - st];
            Ec1 = sc1[tid - st]; Ec2 = sc2[tid - st];
        }
        __syncthreads();
        if (has) {
            float N00, N01, N10, N11, Nc1, Nc2;
            COMPOSE(E00,E01,E10,E11,Ec1,Ec2, r00,r01,r10,r11,rc1,rc2,
                    N00,N01,N10,N11,Nc1,Nc2);
            r00 = N00; r01 = N01; r10 = N10; r11 = N11; rc1 = Nc1; rc2 = Nc2;
            s00[tid] = r00; s01[tid] = r01; s10[tid] = r10; s11[tid] = r11;
            sc1[tid] = rc1; sc2[tid] = rc2;
        }
        __syncthreads();
    }
    float P00 = 1.f, P01 = 0.f, P10 = 0.f, P11 = 1.f, pc1 = 0.f, pc2 = 0.f;
    if (tid > 0) {
        P00 = s00[tid - 1]; P01 = s01[tid - 1];
        P10 = s10[tid - 1]; P11 = s11[tid - 1];
        pc1 = sc1[tid - 1]; pc2 = sc2[tid - 1];
    }
    float2 cin = g_chunkIn[blockIdx.x];
    float st1 = fmaf(P00, cin.x, fmaf(P01, cin.y, pc1));
    float st2 = fmaf(P10, cin.x, fmaf(P11, cin.y, pc2));

    float bx[SPT];
#pragma unroll
    for (int i = 0; i < SPT; i++) bx[i] = g_bx[base + i];
#pragma unroll
    for (int i = 0; i < SPT; i++) {
        out[base + i] = bx[i] + st1;
        float n1 = fmaf(m[i].x, st1, st2) + m[i].z;
        float n2 = fmaf(m[i].y, st1, m[i].w);
        st1 = n1; st2 = n2;
    }
}

// =====================================================================
extern "C" void kernel_launch(void* const* d_in, const int* in_sizes, int n_in,
                              void* d_out, int out_size) {
    const float* f0     = (const float*)d_in[0];
    const float* x      = (const float*)d_in[1];
    const float* params = (const float*)d_in[2];
    const int*   onsets = (const int*)d_in[3];
    float* out = (float*)d_out;

    k_tile<<<Bn * NT, 256>>>(onsets, (const float4*)params);
    k_tileScan<<<1, 1024>>>();
    k_ids<<<Bn * NT, 256>>>(onsets, (const float4*)params);
    k_coef<<<(Bn * Tn) / 256, 256>>>(f0, x);
    k_scanA<<<Bn * NCHUNK, BTH>>>();
    k_scanB<<<1, 1024>>>();
    k_replay<<<Bn * NCHUNK, BTH>>>(out);
}